// round 4
// baseline (speedup 1.0000x reference)
#include <cuda_runtime.h>

// B=2, H=32, G=2048, C=2048, D=128, F=128
#define NPAIR 64
#define GDIM  2048
#define CDIM  2048
#define NCAT  4096
#define DDIM  128
#define FDIM  128

#define OFF_HEAP 0ULL
#define OFF_K    131072ULL
#define OFF_V    16908288ULL
#define OFF_FK   33685504ULL
#define OFF_H    50462720ULL
#define OFF_S    51511296ULL

#define CHUNKS  8
#define CHUNK_G 256            // CDIM / CHUNKS
#define KT      16
#define NT      (CHUNK_G / KT) // 16 tiles

#define NGEMM_BLOCKS   (NPAIR * CHUNKS)            // 512
#define NGATHER_BLOCKS ((NPAIR * GDIM) / 16)       // 8192 (2 rows per warp)

typedef unsigned long long ull;

__device__ ull  g_keys[NPAIR * NCAT];                             // 2 MB
__device__ unsigned int g_order[NPAIR * NCAT];
__device__ float g_partH[(size_t)CHUNKS * NPAIR * FDIM * DDIM];   // 32 MB
__device__ float g_partS[CHUNKS * NPAIR * FDIM];

// ---------------------------------------------------------------------------
__device__ __forceinline__ unsigned int f2key_desc(float s) {
    unsigned int u = __float_as_uint(s);
    unsigned int us = (u & 0x80000000u) ? ~u : (u | 0x80000000u);
    return ~us;
}
__device__ __forceinline__ float key2f(unsigned int hi) {
    unsigned int us = ~hi;
    unsigned int u = (us & 0x80000000u) ? (us ^ 0x80000000u) : ~us;
    return __uint_as_float(u);
}
__device__ __forceinline__ void cswap(ull& a, ull& b, bool up) {
    if ((a > b) == up) { ull t = a; a = b; b = t; }
}

// ---------------------------------------------------------------------------
// Sort phase A: 128 CTAs; CTA (pair, half) bitonic-sorts its 2048 keys.
// half 0 ascending (by key), half 1 descending -> global bitonic sequence.
// ---------------------------------------------------------------------------
__global__ void __launch_bounds__(512) sortA_kernel(
    const float* __restrict__ heap_score,
    const float* __restrict__ win_score)
{
    __shared__ ull sk[2048];   // 16 KB
    const int pair = blockIdx.x >> 1;
    const int half = blockIdx.x & 1;
    const int tid  = threadIdx.x;
    const bool desc = (half == 1);

    float4 sc = (half == 0)
        ? ((const float4*)(heap_score + (size_t)pair * GDIM))[tid]
        : ((const float4*)(win_score  + (size_t)pair * CDIM))[tid];

    ull e[4];
    {
        const int p = half * 2048 + 4 * tid;   // global concat position
        e[0] = ((ull)f2key_desc(sc.x) << 32) | (unsigned)(p + 0);
        e[1] = ((ull)f2key_desc(sc.y) << 32) | (unsigned)(p + 1);
        e[2] = ((ull)f2key_desc(sc.z) << 32) | (unsigned)(p + 2);
        e[3] = ((ull)f2key_desc(sc.w) << 32) | (unsigned)(p + 3);
    }

    // k = 2
    cswap(e[0], e[1], !desc);
    cswap(e[2], e[3], desc);

    for (int k = 4; k <= 2048; k <<= 1) {
        const bool up = (((tid & (k >> 2)) == 0) != desc);
        for (int j = k >> 1; j >= 4; j >>= 1) {
            if (j >= 128) {
                const int base = 4 * tid;
                sk[base + 0] = e[0]; sk[base + 1] = e[1];
                sk[base + 2] = e[2]; sk[base + 3] = e[3];
                __syncthreads();
                const int pt = (tid ^ (j >> 2)) * 4;
                const bool lower = ((tid & (j >> 2)) == 0);
                ull p0 = sk[pt], p1 = sk[pt + 1], p2 = sk[pt + 2], p3 = sk[pt + 3];
                if (lower == up) {
                    e[0] = e[0] < p0 ? e[0] : p0;  e[1] = e[1] < p1 ? e[1] : p1;
                    e[2] = e[2] < p2 ? e[2] : p2;  e[3] = e[3] < p3 ? e[3] : p3;
                } else {
                    e[0] = e[0] > p0 ? e[0] : p0;  e[1] = e[1] > p1 ? e[1] : p1;
                    e[2] = e[2] > p2 ? e[2] : p2;  e[3] = e[3] > p3 ? e[3] : p3;
                }
                __syncthreads();
            } else {
                const int w = j >> 2;
                const bool lower = ((tid & w) == 0);
                #pragma unroll
                for (int s = 0; s < 4; ++s) {
                    ull p = __shfl_xor_sync(0xffffffffu, e[s], w);
                    e[s] = (lower == up) ? (e[s] < p ? e[s] : p)
                                         : (e[s] > p ? e[s] : p);
                }
            }
        }
        cswap(e[0], e[2], up); cswap(e[1], e[3], up);
        cswap(e[0], e[1], up); cswap(e[2], e[3], up);
    }

    const int base = pair * NCAT + half * 2048 + 4 * tid;
    g_keys[base + 0] = e[0]; g_keys[base + 1] = e[1];
    g_keys[base + 2] = e[2]; g_keys[base + 3] = e[3];
}

// ---------------------------------------------------------------------------
// Sort phase B: j=2048 exchange across halves (gmem, L2-hot) + local merge.
// Result: fully ascending-by-key = descending-by-score. Half 0 = top block.
// ---------------------------------------------------------------------------
__global__ void __launch_bounds__(512) sortB_kernel(float* __restrict__ out_heap)
{
    __shared__ ull sk[2048];
    const int pair = blockIdx.x >> 1;
    const int half = blockIdx.x & 1;
    const int tid  = threadIdx.x;

    const int mybase = pair * NCAT + half * 2048 + 4 * tid;
    const int ptbase = pair * NCAT + (half ^ 1) * 2048 + 4 * tid;

    ull e[4], p[4];
    #pragma unroll
    for (int s = 0; s < 4; ++s) { e[s] = g_keys[mybase + s]; p[s] = g_keys[ptbase + s]; }
    if (half == 0) {
        #pragma unroll
        for (int s = 0; s < 4; ++s) e[s] = e[s] < p[s] ? e[s] : p[s];
    } else {
        #pragma unroll
        for (int s = 0; s < 4; ++s) e[s] = e[s] > p[s] ? e[s] : p[s];
    }

    // local bitonic merge, ascending: j = 1024..128 via smem
    #pragma unroll
    for (int j = 1024; j >= 128; j >>= 1) {
        const int base = 4 * tid;
        sk[base + 0] = e[0]; sk[base + 1] = e[1];
        sk[base + 2] = e[2]; sk[base + 3] = e[3];
        __syncthreads();
        const int pt = (tid ^ (j >> 2)) * 4;
        const bool lower = ((tid & (j >> 2)) == 0);
        ull q0 = sk[pt], q1 = sk[pt + 1], q2 = sk[pt + 2], q3 = sk[pt + 3];
        if (lower) {
            e[0] = e[0] < q0 ? e[0] : q0;  e[1] = e[1] < q1 ? e[1] : q1;
            e[2] = e[2] < q2 ? e[2] : q2;  e[3] = e[3] < q3 ? e[3] : q3;
        } else {
            e[0] = e[0] > q0 ? e[0] : q0;  e[1] = e[1] > q1 ? e[1] : q1;
            e[2] = e[2] > q2 ? e[2] : q2;  e[3] = e[3] > q3 ? e[3] : q3;
        }
        __syncthreads();
    }
    // j = 64..4 via shfl
    #pragma unroll
    for (int j = 64; j >= 4; j >>= 1) {
        const int w = j >> 2;
        const bool lower = ((tid & w) == 0);
        #pragma unroll
        for (int s = 0; s < 4; ++s) {
            ull q = __shfl_xor_sync(0xffffffffu, e[s], w);
            e[s] = lower ? (e[s] < q ? e[s] : q) : (e[s] > q ? e[s] : q);
        }
    }
    // j = 2, 1
    cswap(e[0], e[2], true); cswap(e[1], e[3], true);
    cswap(e[0], e[1], true); cswap(e[2], e[3], true);

    g_order[mybase + 0] = (unsigned)e[0];
    g_order[mybase + 1] = (unsigned)e[1];
    g_order[mybase + 2] = (unsigned)e[2];
    g_order[mybase + 3] = (unsigned)e[3];
    if (half == 0) {
        float4 hs;
        hs.x = key2f((unsigned)(e[0] >> 32));
        hs.y = key2f((unsigned)(e[1] >> 32));
        hs.z = key2f((unsigned)(e[2] >> 32));
        hs.w = key2f((unsigned)(e[3] >> 32));
        ((float4*)(out_heap + (size_t)pair * GDIM))[tid] = hs;
    }
}

// ---------------------------------------------------------------------------
__device__ __forceinline__ ull fma2(ull a, ull b, ull c) {
    ull d;
    asm("fma.rn.f32x2 %0, %1, %2, %3;" : "=l"(d) : "l"(a), "l"(b), "l"(c));
    return d;
}
__device__ __forceinline__ ull pack2(float lo, float hi) {
    ull r;
    asm("mov.b64 %0, {%1, %2};" : "=l"(r) : "f"(lo), "f"(hi));
    return r;
}
__device__ __forceinline__ void cp16(void* smem_dst, const void* gsrc) {
    unsigned s = (unsigned)__cvta_generic_to_shared(smem_dst);
    asm volatile("cp.async.cg.shared.global [%0], [%1], 16;\n" :: "r"(s), "l"(gsrc));
}

// ---------------------------------------------------------------------------
// Fused: gemm CTAs (512, first) + gather CTAs (8192).
// ---------------------------------------------------------------------------
__global__ void __launch_bounds__(256, 2) fused_kernel(
    const float* __restrict__ K_top, const float* __restrict__ V_top,
    const float* __restrict__ FK_top,
    const float* __restrict__ K_win, const float* __restrict__ V_win,
    const float* __restrict__ FK_win,
    float* __restrict__ out)
{
    __shared__ float FKs[2][KT][FDIM];
    __shared__ float Vs [2][KT][DDIM];

    if (blockIdx.x < NGEMM_BLOCKS) {
        // ============================ GEMM ============================
        const int pair  = blockIdx.x & (NPAIR - 1);
        const int chunk = blockIdx.x >> 6;
        const int tid   = threadIdx.x;
        const int tx    = tid & 15;      // d: tx*4 and 64+tx*4
        const int ty    = tid >> 4;      // f: ty*8..ty*8+7; row loader id
        const int g0    = chunk * CHUNK_G;
        const int obase = pair * NCAT + GDIM + g0;

        ull accp[8][4];
        float s_acc[8];
        #pragma unroll
        for (int i = 0; i < 8; ++i) {
            s_acc[i] = 0.0f;
            #pragma unroll
            for (int j = 0; j < 4; ++j) accp[i][j] = pack2(0.0f, 0.0f);
        }

        auto issue_tile = [&](int kt, int buf) {
            const unsigned idx = g_order[obase + kt * KT + ty];
            const float *fsrc, *vsrc;
            if (idx < GDIM) {
                const size_t r = (size_t)pair * GDIM + idx;
                fsrc = FK_top + r * FDIM;  vsrc = V_top + r * DDIM;
            } else {
                const size_t r = (size_t)pair * CDIM + (idx - GDIM);
                fsrc = FK_win + r * FDIM;  vsrc = V_win + r * DDIM;
            }
            cp16(&FKs[buf][ty][tx * 4],        fsrc + tx * 4);
            cp16(&FKs[buf][ty][(tx + 16) * 4], fsrc + (tx + 16) * 4);
            cp16(&Vs [buf][ty][tx * 4],        vsrc + tx * 4);
            cp16(&Vs [buf][ty][(tx + 16) * 4], vsrc + (tx + 16) * 4);
        };

        issue_tile(0, 0);
        asm volatile("cp.async.commit_group;\n");

        for (int kt = 0; kt < NT; ++kt) {
            const int buf = kt & 1;
            if (kt + 1 < NT) {
                issue_tile(kt + 1, buf ^ 1);
                asm volatile("cp.async.commit_group;\n");
                asm volatile("cp.async.wait_group 1;\n");
            } else {
                asm volatile("cp.async.wait_group 0;\n");
            }
            __syncthreads();

            #pragma unroll
            for (int kk = 0; kk < KT; ++kk) {
                float fv[8];
                *(float4*)&fv[0] = *(const float4*)&FKs[buf][kk][ty * 8];
                *(float4*)&fv[4] = *(const float4*)&FKs[buf][kk][ty * 8 + 4];
                ull vp[4];
                {   // direct 64-bit pair loads, no packing movs
                    const ulonglong2 va = *(const ulonglong2*)&Vs[buf][kk][tx * 4];
                    const ulonglong2 vb = *(const ulonglong2*)&Vs[buf][kk][64 + tx * 4];
                    vp[0] = va.x; vp[1] = va.y; vp[2] = vb.x; vp[3] = vb.y;
                }
                #pragma unroll
                for (int i = 0; i < 8; ++i) {
                    ull fp = pack2(fv[i], fv[i]);
                    #pragma unroll
                    for (int j = 0; j < 4; ++j)
                        accp[i][j] = fma2(fp, vp[j], accp[i][j]);
                }
                if (tx == 0) {
                    #pragma unroll
                    for (int i = 0; i < 8; ++i) s_acc[i] += fv[i];
                }
            }
            __syncthreads();
        }

        float* Hp = g_partH + ((size_t)(chunk * NPAIR + pair)) * (FDIM * DDIM);
        #pragma unroll
        for (int i = 0; i < 8; ++i) {
            const int f = ty * 8 + i;
            *(ull*)&Hp[f * DDIM + tx * 4]          = accp[i][0];
            *(ull*)&Hp[f * DDIM + tx * 4 + 2]      = accp[i][1];
            *(ull*)&Hp[f * DDIM + 64 + tx * 4]     = accp[i][2];
            *(ull*)&Hp[f * DDIM + 64 + tx * 4 + 2] = accp[i][3];
        }
        if (tx == 0) {
            float* Sp = g_partS + (chunk * NPAIR + pair) * FDIM;
            #pragma unroll
            for (int i = 0; i < 8; ++i) Sp[ty * 8 + i] = s_acc[i];
        }
    } else {
        // =========================== GATHER ===========================
        const int gb   = blockIdx.x - NGEMM_BLOCKS;
        const int warp = threadIdx.x >> 5;
        const int lane = threadIdx.x & 31;
        const int rowid0 = (gb * 8 + warp) * 2;
        const int pair   = rowid0 >> 11;
        const int g      = rowid0 & (GDIM - 1);

        const unsigned idx0 = g_order[pair * NCAT + g];
        const unsigned idx1 = g_order[pair * NCAT + g + 1];

        const float4 *k0, *v0, *f0, *k1, *v1, *f1;
        if (idx0 < GDIM) {
            const size_t r = (size_t)pair * GDIM + idx0;
            k0 = (const float4*)(K_top + r * 128);
            v0 = (const float4*)(V_top + r * 128);
            f0 = (const float4*)(FK_top + r * 128);
        } else {
            const size_t r = (size_t)pair * CDIM + (idx0 - GDIM);
            k0 = (const float4*)(K_win + r * 128);
            v0 = (const float4*)(V_win + r * 128);
            f0 = (const float4*)(FK_win + r * 128);
        }
        if (idx1 < GDIM) {
            const size_t r = (size_t)pair * GDIM + idx1;
            k1 = (const float4*)(K_top + r * 128);
            v1 = (const float4*)(V_top + r * 128);
            f1 = (const float4*)(FK_top + r * 128);
        } else {
            const size_t r = (size_t)pair * CDIM + (idx1 - GDIM);
            k1 = (const float4*)(K_win + r * 128);
            v1 = (const float4*)(V_win + r * 128);
            f1 = (const float4*)(FK_win + r * 128);
        }
        float4 a = k0[lane], b = v0[lane], c = f0[lane];
        float4 d = k1[lane], e = v1[lane], f = f1[lane];
        ((float4*)(out + OFF_K  + (size_t)rowid0 * 128))[lane]       = a;
        ((float4*)(out + OFF_V  + (size_t)rowid0 * 128))[lane]       = b;
        ((float4*)(out + OFF_FK + (size_t)rowid0 * 128))[lane]       = c;
        ((float4*)(out + OFF_K  + (size_t)(rowid0 + 1) * 128))[lane] = d;
        ((float4*)(out + OFF_V  + (size_t)(rowid0 + 1) * 128))[lane] = e;
        ((float4*)(out + OFF_FK + (size_t)(rowid0 + 1) * 128))[lane] = f;
    }
}

// ---------------------------------------------------------------------------
__global__ void __launch_bounds__(256) reduce_kernel(float* __restrict__ out)
{
    const int NH = NPAIR * FDIM * DDIM;   // 1048576
    const int NS = NPAIR * FDIM;          // 8192
    int i = blockIdx.x * blockDim.x + threadIdx.x;
    if (i < NH) {
        float s = 0.0f;
        #pragma unroll
        for (int c = 0; c < CHUNKS; ++c) s += g_partH[(size_t)c * NH + i];
        out[OFF_H + i] = s;
    } else if (i < NH + NS) {
        int j = i - NH;
        float s = 0.0f;
        #pragma unroll
        for (int c = 0; c < CHUNKS; ++c) s += g_partS[c * NS + j];
        out[OFF_S + j] = s;
    }
}

// ---------------------------------------------------------------------------
extern "C" void kernel_launch(void* const* d_in, const int* in_sizes, int n_in,
                              void* d_out, int out_size)
{
    const float* K_top      = (const float*)d_in[0];
    const float* V_top      = (const float*)d_in[1];
    const float* FK_top     = (const float*)d_in[2];
    const float* heap_score = (const float*)d_in[3];
    const float* K_win      = (const float*)d_in[4];
    const float* V_win      = (const float*)d_in[5];
    const float* FK_win     = (const float*)d_in[6];
    const float* win_score  = (const float*)d_in[7];
    float* out = (float*)d_out;

    sortA_kernel<<<NPAIR * 2, 512>>>(heap_score, win_score);
    sortB_kernel<<<NPAIR * 2, 512>>>(out + OFF_HEAP);

    fused_kernel<<<NGEMM_BLOCKS + NGATHER_BLOCKS, 256>>>(
        K_top, V_top, FK_top, K_win, V_win, FK_win, out);

    const int NTOT = NPAIR * FDIM * DDIM + NPAIR * FDIM;
    reduce_kernel<<<(NTOT + 255) / 256, 256>>>(out);
}